// round 10
// baseline (speedup 1.0000x reference)
#include <cuda_runtime.h>
#include <cuda_bf16.h>

// Problem constants
#define B_    8
#define N_    8192
#define DIN   13
#define M_    2048
#define KNB   32
#define R2    0.04f

// Output layout (single float32 buffer, outputs concatenated in return order):
//   x_out  [B][M][128]  floats
//   pos_s  [B][M][3]    floats
//   batch_s[B][M]       floats (values 0..7, exact)
#define X_OUT_OFF 0
#define POS_S_OFF (B_ * M_ * 128)            // 2097152
#define BATCH_OFF (POS_S_OFF + B_ * M_ * 3)  // 2146304

// Per-cloud FPS progress: g_iter[b] = (last completed iteration) + 1.
// Reset to 0 by a memset node at the head of the graph on every replay.
__device__ unsigned g_iter[B_];

// ---------------------------------------------------------------------------
// Distance with NO fma contraction: must bit-match jnp.sum((a-b)**2, -1)
// ---------------------------------------------------------------------------
__device__ __forceinline__ float d2_exact(float ax, float ay, float az,
                                          float bx, float by, float bz) {
    float dx = ax - bx, dy = ay - by, dz = az - bz;
    return __fadd_rn(__fadd_rn(__fmul_rn(dx, dx), __fmul_rn(dy, dy)),
                     __fmul_rn(dz, dz));
}

__device__ __forceinline__ unsigned smem_u32(const void* p) {
    return (unsigned)__cvta_generic_to_shared(p);
}

// ===========================================================================
// FPS role: cluster of 8 CTAs per batch element (blocks 0..63).
// Identical to the Round-6 design (best measured): two-stage reduce
// (warp redux -> smem -> block redux) then 8-arrival DSMEM exchange with
// mbarrier (count=8) + try_wait sleep. After writing each selected center
// to pos_s/batch_s, rank0/tid0 publishes progress with st.release.gpu.
// ===========================================================================
#define FPS_CTAS 8
#define FPS_THR  256
#define FPS_TOT  (FPS_CTAS * FPS_THR)   // 2048
#define FPS_PPT  (N_ / FPS_TOT)         // 4

__device__ __forceinline__ void fps_role(const float* __restrict__ pos,
                                         float* __restrict__ out) {
    const int rank = blockIdx.x % FPS_CTAS;
    const int b    = blockIdx.x / FPS_CTAS;
    const int tid  = threadIdx.x;
    const int lane = tid & 31;
    const int wid  = tid >> 5;
    const float* posb = pos + (size_t)b * N_ * 3;

    __shared__ unsigned long long s_mbar;
    __shared__ uint2              s_wslot[2][FPS_THR / 32];
    __shared__ unsigned long long s_cslot[2][FPS_CTAS];

    const unsigned mbar_addr = smem_u32(&s_mbar);
    if (tid == 0) {
        asm volatile("mbarrier.init.shared.b64 [%0], %1;"
                     :: "r"(mbar_addr), "r"(FPS_CTAS) : "memory");
    }
    __syncthreads();
    // All cluster mbarriers initialized before any peer arrives on them.
    asm volatile("barrier.cluster.arrive.aligned;" ::: "memory");
    asm volatile("barrier.cluster.wait.aligned;" ::: "memory");

    float px[FPS_PPT], py[FPS_PPT], pz[FPS_PPT], mind[FPS_PPT];
    const int tg = rank * FPS_THR + tid;    // thread id within the cloud
#pragma unroll
    for (int k = 0; k < FPS_PPT; k++) {
        int g = tg + k * FPS_TOT;
        px[k]   = posb[g * 3 + 0];
        py[k]   = posb[g * 3 + 1];
        pz[k]   = posb[g * 3 + 2];
        mind[k] = 1e10f;
    }

    // First sample is index 0.
    float qx = posb[0], qy = posb[1], qz = posb[2];
    if (rank == 0 && tid == 0) {
        size_t o = POS_S_OFF + ((size_t)b * M_) * 3;
        out[o + 0] = qx; out[o + 1] = qy; out[o + 2] = qz;
        out[BATCH_OFF + (size_t)b * M_] = (float)b;
        asm volatile("st.release.gpu.u32 [%0], %1;"
                     :: "l"(&g_iter[b]), "r"(1u) : "memory");
    }

    for (int it = 1; it < M_; it++) {
        const int buf = it & 1;

        // --- per-thread update + argmax (smallest index on ties) ----------
        float bv = -1.0f; int bi = 0;
#pragma unroll
        for (int k = 0; k < FPS_PPT; k++) {
            float d  = d2_exact(px[k], py[k], pz[k], qx, qy, qz);
            float mv = fminf(mind[k], d);
            mind[k]  = mv;
            if (mv > bv) { bv = mv; bi = tg + k * FPS_TOT; }
        }
        unsigned vb = __float_as_uint(bv);   // bv >= 0 -> monotonic bits

        // --- warp reduce: max value, then min index among ties ------------
        unsigned wmax = __reduce_max_sync(0xffffffffu, vb);
        unsigned cand = (vb == wmax) ? (unsigned)bi : 0xffffffffu;
        unsigned widx = __reduce_min_sync(0xffffffffu, cand);
        if (lane == 0) s_wslot[buf][wid] = make_uint2(wmax, widx);
        __syncthreads();

        // --- block reduce over 8 warp slots (all warps redundantly) -------
        uint2 ws = s_wslot[buf][lane & (FPS_THR / 32 - 1)];
        unsigned bmax = __reduce_max_sync(0xffffffffu, ws.x);
        cand = (ws.x == bmax) ? ws.y : 0xffffffffu;
        unsigned bidx = __reduce_min_sync(0xffffffffu, cand);

        // --- cluster exchange: broadcast block winner to all 8 peers ------
        if (tid < FPS_CTAS) {
            unsigned long long key =
                ((unsigned long long)bmax << 32) | (unsigned long long)bidx;
            unsigned slot = smem_u32(&s_cslot[buf][rank]);
            asm volatile(
                "{\n\t.reg .b32 ra, rb;\n\t"
                "mapa.shared::cluster.u32 ra, %0, %2;\n\t"
                "st.shared::cluster.b64 [ra], %1;\n\t"
                "mapa.shared::cluster.u32 rb, %3, %2;\n\t"
                "mbarrier.arrive.release.cluster.shared::cluster.b64 _, [rb];\n\t"
                "}"
                :: "r"(slot), "l"(key), "r"(tid), "r"(mbar_addr) : "memory");
        }
        // wait for 8 arrivals; phase parity alternates per iteration
        {
            unsigned parity = (unsigned)((it - 1) & 1);
            asm volatile(
                "{\n\t.reg .pred P1;\n\t"
                "WAIT_%=:\n\t"
                "mbarrier.try_wait.parity.acquire.cluster.shared::cta.b64 P1, [%0], %1;\n\t"
                "@P1 bra DONE_%=;\n\t"
                "bra WAIT_%=;\n\t"
                "DONE_%=:\n\t}"
                :: "r"(mbar_addr), "r"(parity) : "memory");
        }

        // --- cluster reduce over 8 slots (all threads redundantly) --------
        unsigned long long cs = s_cslot[buf][lane & (FPS_CTAS - 1)];
        unsigned cv = (unsigned)(cs >> 32);
        unsigned ci = (unsigned)cs;
        unsigned gmax = __reduce_max_sync(0xffffffffu, cv);
        cand = (cv == gmax) ? ci : 0xffffffffu;
        unsigned gidx = __reduce_min_sync(0xffffffffu, cand);

        qx = posb[gidx * 3 + 0];   // broadcast load, L1-resident
        qy = posb[gidx * 3 + 1];
        qz = posb[gidx * 3 + 2];
        if (rank == 0 && tid == 0) {
            size_t o = POS_S_OFF + ((size_t)b * M_ + it) * 3;
            out[o + 0] = qx; out[o + 1] = qy; out[o + 2] = qz;
            out[BATCH_OFF + (size_t)b * M_ + it] = (float)b;
            asm volatile("st.release.gpu.u32 [%0], %1;"
                         :: "l"(&g_iter[b]), "r"((unsigned)(it + 1)) : "memory");
        }
    }

    asm volatile("barrier.cluster.arrive.aligned;" ::: "memory");
    asm volatile("barrier.cluster.wait.aligned;" ::: "memory");
}

// ===========================================================================
// SA role: blocks 64..2111. Block k (= blockIdx-64) handles center m=k of
// ALL 8 clouds (warp = cloud b), so each block's readiness == fps iteration
// k and block launch order matches readiness order. Warps poll g_iter[b]
// with ld.acquire.gpu + nanosleep until center (b, k) is published, then
// run: ball query (first K by index) + gather + 2-layer MLP + masked max.
// (MLP body identical to the Round-6 sa_kernel, measured 448 us.)
// ===========================================================================
__device__ __forceinline__ void sa_role(const float* __restrict__ x,
                                        const float* __restrict__ pos,
                                        const float* __restrict__ W1,
                                        const float* __restrict__ b1,
                                        const float* __restrict__ W2,
                                        const float* __restrict__ b2,
                                        float* __restrict__ out) {
    __shared__ __align__(16) float sW1[64][16];    // W1^T
    __shared__ float sb1[64];
    __shared__ __align__(16) float sW2[128][64];   // W2^T
    __shared__ float sb2[128];
    __shared__ int   s_nbr[8][KNB];

    const int tid = threadIdx.x;
    for (int i = tid; i < 64 * 16; i += 256) {
        int j = i >> 4, k = i & 15;
        sW1[j][k] = W1[k * 64 + j];
    }
    for (int i = tid; i < 128 * 64; i += 256) {
        int j = i >> 6, k = i & 63;
        sW2[j][k] = W2[k * 128 + j];
    }
    if (tid < 64)  sb1[tid] = b1[tid];
    if (tid < 128) sb2[tid] = b2[tid];
    __syncthreads();

    const int warp = tid >> 5;
    const int lane = tid & 31;
    const int b    = warp;                    // cloud
    const int m    = blockIdx.x - 64;         // center index within cloud
    const int c    = b * M_ + m;              // global center id
    const float* posb = pos + (size_t)b * N_ * 3;
    const float* xb   = x   + (size_t)b * N_ * DIN;

    // --- wait until fps has published center (b, m) ------------------------
    {
        const unsigned need = (unsigned)(m + 1);
        unsigned v;
        for (;;) {
            asm volatile("ld.acquire.gpu.u32 %0, [%1];"
                         : "=r"(v) : "l"(&g_iter[b]) : "memory");
            if (v >= need) break;
            __nanosleep(128);
        }
    }

    const float cx = out[POS_S_OFF + (size_t)c * 3 + 0];
    const float cy = out[POS_S_OFF + (size_t)c * 3 + 1];
    const float cz = out[POS_S_OFF + (size_t)c * 3 + 2];

    // --- Ball query: first KNB in-ball points by ascending index ----------
    int count = 0;
    for (int base = 0; base < N_ && count < KNB; base += 32) {
        const int n = base + lane;
        float d = d2_exact(posb[n * 3 + 0], posb[n * 3 + 1], posb[n * 3 + 2],
                           cx, cy, cz);
        const bool within = (d <= R2);
        const unsigned mask = __ballot_sync(0xffffffffu, within);
        const int pre = __popc(mask & ((1u << lane) - 1u));
        if (within && (count + pre) < KNB) s_nbr[warp][count + pre] = n;
        count += __popc(mask);
        if (count > KNB) count = KNB;
    }
    __syncwarp();
    const bool valid = (lane < count);
    const int  nbr   = valid ? s_nbr[warp][lane] : s_nbr[warp][0];

    // --- Gather features ---------------------------------------------------
    float f[16];
#pragma unroll
    for (int k = 0; k < DIN; k++) f[k] = xb[(size_t)nbr * DIN + k];
    f[13] = posb[nbr * 3 + 0] - cx;
    f[14] = posb[nbr * 3 + 1] - cy;
    f[15] = posb[nbr * 3 + 2] - cz;

    // --- Layer 1: 16 -> 64, ReLU (h1 stays in registers) -------------------
    float h1[64];
#pragma unroll
    for (int j = 0; j < 64; j++) {
        float acc = sb1[j];
        const float4* w = reinterpret_cast<const float4*>(&sW1[j][0]);
#pragma unroll
        for (int k4 = 0; k4 < 4; k4++) {
            float4 w4 = w[k4];
            acc = fmaf(f[4 * k4 + 0], w4.x, acc);
            acc = fmaf(f[4 * k4 + 1], w4.y, acc);
            acc = fmaf(f[4 * k4 + 2], w4.z, acc);
            acc = fmaf(f[4 * k4 + 3], w4.w, acc);
        }
        h1[j] = fmaxf(acc, 0.0f);
    }

    // --- Layer 2: 64 -> 128, ReLU, masked warp-max (redux.sync) ------------
    float r0, r1, r2, r3;
#pragma unroll
    for (int jo = 0; jo < 4; jo++) {
#pragma unroll 1
        for (int ji = 0; ji < 32; ji++) {
            const int j = jo * 32 + ji;
            float a0 = sb2[j], a1 = 0.0f;
            const float4* w = reinterpret_cast<const float4*>(&sW2[j][0]);
#pragma unroll
            for (int k4 = 0; k4 < 8; k4++) {
                float4 wA = w[k4];
                float4 wB = w[k4 + 8];
                a0 = fmaf(h1[4 * k4 + 0],      wA.x, a0);
                a0 = fmaf(h1[4 * k4 + 1],      wA.y, a0);
                a0 = fmaf(h1[4 * k4 + 2],      wA.z, a0);
                a0 = fmaf(h1[4 * k4 + 3],      wA.w, a0);
                a1 = fmaf(h1[32 + 4 * k4 + 0], wB.x, a1);
                a1 = fmaf(h1[32 + 4 * k4 + 1], wB.y, a1);
                a1 = fmaf(h1[32 + 4 * k4 + 2], wB.z, a1);
                a1 = fmaf(h1[32 + 4 * k4 + 3], wB.w, a1);
            }
            float acc = fmaxf(a0 + a1, 0.0f);
            // invalid slots contribute 0: safe because ReLU >= 0 and the
            // center itself is always a valid neighbor (d^2 = 0 <= R^2).
            if (!valid) acc = 0.0f;
            // acc >= 0 -> f32 bits monotonic under unsigned max
            unsigned red = __reduce_max_sync(0xffffffffu, __float_as_uint(acc));
            if (lane == ji) {
                float rv = __uint_as_float(red);
                if (jo == 0) r0 = rv;
                else if (jo == 1) r1 = rv;
                else if (jo == 2) r2 = rv;
                else r3 = rv;
            }
        }
    }

    float* o = out + X_OUT_OFF + (size_t)c * 128;
    o[lane +  0] = r0;
    o[lane + 32] = r1;
    o[lane + 64] = r2;
    o[lane + 96] = r3;
}

// ===========================================================================
// Fused kernel: blocks 0..63 = FPS (8 clusters x 8 CTAs), blocks 64..2111
// = SA consumers. Uniform 256 threads; cluster dims 8 (sa clusters inert).
// FPS blocks are wave-1 resident (<=296 slots), so sa's polling can never
// starve fps -> no deadlock; forward progress is monotone in g_iter.
// ===========================================================================
#define SA_BLOCKS (M_)               // 2048
#define GRID_TOT  (64 + SA_BLOCKS)   // 2112 (divisible by 8)

__global__ void __launch_bounds__(256)
__cluster_dims__(FPS_CTAS, 1, 1)
fused_kernel(const float* __restrict__ x, const float* __restrict__ pos,
             const float* __restrict__ W1, const float* __restrict__ b1,
             const float* __restrict__ W2, const float* __restrict__ b2,
             float* __restrict__ out) {
    if (blockIdx.x < 64) {
        fps_role(pos, out);
    } else {
        sa_role(x, pos, W1, b1, W2, b2, out);
    }
}

// ===========================================================================
extern "C" void kernel_launch(void* const* d_in, const int* in_sizes, int n_in,
                              void* d_out, int out_size) {
    (void)in_sizes; (void)n_in; (void)out_size;
    const float* x   = (const float*)d_in[0];   // [B, N, 13]
    const float* pos = (const float*)d_in[1];   // [B, N, 3]
    // d_in[2] = batch (int32) — always broadcast arange(B), recomputed directly
    const float* W1  = (const float*)d_in[3];   // [16, 64]
    const float* b1  = (const float*)d_in[4];   // [64]
    const float* W2  = (const float*)d_in[5];   // [64, 128]
    const float* b2  = (const float*)d_in[6];   // [128]
    float* out = (float*)d_out;

    // Reset fps progress flags on every graph replay (stale flags + poisoned
    // output buffer would otherwise let sa read garbage centers).
    void* p_iter = nullptr;
    cudaGetSymbolAddress(&p_iter, g_iter);
    cudaMemsetAsync(p_iter, 0, sizeof(unsigned) * B_, 0);

    fused_kernel<<<GRID_TOT, 256>>>(x, pos, W1, b1, W2, b2, out);
}

// round 12
// speedup vs baseline: 1.1351x; 1.1351x over previous
#include <cuda_runtime.h>
#include <cuda_bf16.h>

// Problem constants
#define B_    8
#define N_    8192
#define DIN   13
#define M_    2048
#define KNB   32
#define R2    0.04f

// Output layout (single float32 buffer, outputs concatenated in return order):
//   x_out  [B][M][128]  floats
//   pos_s  [B][M][3]    floats
//   batch_s[B][M]       floats (values 0..7, exact)
#define X_OUT_OFF 0
#define POS_S_OFF (B_ * M_ * 128)            // 2097152
#define BATCH_OFF (POS_S_OFF + B_ * M_ * 3)  // 2146304

// Per-cloud FPS progress: g_iter[b] = (last completed iteration) + 1.
// Reset to 0 by a memset node at the head of the graph on every replay.
__device__ unsigned g_iter[B_];

#define SA_WORKERS 80
#define GRID_TOT   (64 + SA_WORKERS)   // 144 blocks = 18 clusters of 8, <=148 SMs

// ---------------------------------------------------------------------------
// Distance with NO fma contraction: must bit-match jnp.sum((a-b)**2, -1)
// ---------------------------------------------------------------------------
__device__ __forceinline__ float d2_exact(float ax, float ay, float az,
                                          float bx, float by, float bz) {
    float dx = ax - bx, dy = ay - by, dz = az - bz;
    return __fadd_rn(__fadd_rn(__fmul_rn(dx, dx), __fmul_rn(dy, dy)),
                     __fmul_rn(dz, dz));
}

__device__ __forceinline__ unsigned smem_u32(const void* p) {
    return (unsigned)__cvta_generic_to_shared(p);
}

// ===========================================================================
// FPS role: cluster of 8 CTAs per batch element (blocks 0..63).
// Identical to the Round-6 design (best measured 1726us): two-stage reduce
// (warp redux -> smem -> block redux) then 8-arrival DSMEM exchange with
// mbarrier (count=8) + try_wait sleep. After writing each selected center,
// rank0/tid0 publishes progress with st.release.gpu.
// ===========================================================================
#define FPS_CTAS 8
#define FPS_THR  256
#define FPS_TOT  (FPS_CTAS * FPS_THR)   // 2048
#define FPS_PPT  (N_ / FPS_TOT)         // 4

__device__ __forceinline__ void fps_role(const float* __restrict__ pos,
                                         float* __restrict__ out) {
    const int rank = blockIdx.x % FPS_CTAS;
    const int b    = blockIdx.x / FPS_CTAS;
    const int tid  = threadIdx.x;
    const int lane = tid & 31;
    const int wid  = tid >> 5;
    const float* posb = pos + (size_t)b * N_ * 3;

    __shared__ unsigned long long s_mbar;
    __shared__ uint2              s_wslot[2][FPS_THR / 32];
    __shared__ unsigned long long s_cslot[2][FPS_CTAS];

    const unsigned mbar_addr = smem_u32(&s_mbar);
    if (tid == 0) {
        asm volatile("mbarrier.init.shared.b64 [%0], %1;"
                     :: "r"(mbar_addr), "r"(FPS_CTAS) : "memory");
    }
    __syncthreads();
    // All cluster mbarriers initialized before any peer arrives on them.
    asm volatile("barrier.cluster.arrive.aligned;" ::: "memory");
    asm volatile("barrier.cluster.wait.aligned;" ::: "memory");

    float px[FPS_PPT], py[FPS_PPT], pz[FPS_PPT], mind[FPS_PPT];
    const int tg = rank * FPS_THR + tid;    // thread id within the cloud
#pragma unroll
    for (int k = 0; k < FPS_PPT; k++) {
        int g = tg + k * FPS_TOT;
        px[k]   = posb[g * 3 + 0];
        py[k]   = posb[g * 3 + 1];
        pz[k]   = posb[g * 3 + 2];
        mind[k] = 1e10f;
    }

    // First sample is index 0.
    float qx = posb[0], qy = posb[1], qz = posb[2];
    if (rank == 0 && tid == 0) {
        size_t o = POS_S_OFF + ((size_t)b * M_) * 3;
        out[o + 0] = qx; out[o + 1] = qy; out[o + 2] = qz;
        out[BATCH_OFF + (size_t)b * M_] = (float)b;
        asm volatile("st.release.gpu.u32 [%0], %1;"
                     :: "l"(&g_iter[b]), "r"(1u) : "memory");
    }

    for (int it = 1; it < M_; it++) {
        const int buf = it & 1;

        // --- per-thread update + argmax (smallest index on ties) ----------
        float bv = -1.0f; int bi = 0;
#pragma unroll
        for (int k = 0; k < FPS_PPT; k++) {
            float d  = d2_exact(px[k], py[k], pz[k], qx, qy, qz);
            float mv = fminf(mind[k], d);
            mind[k]  = mv;
            if (mv > bv) { bv = mv; bi = tg + k * FPS_TOT; }
        }
        unsigned vb = __float_as_uint(bv);   // bv >= 0 -> monotonic bits

        // --- warp reduce: max value, then min index among ties ------------
        unsigned wmax = __reduce_max_sync(0xffffffffu, vb);
        unsigned cand = (vb == wmax) ? (unsigned)bi : 0xffffffffu;
        unsigned widx = __reduce_min_sync(0xffffffffu, cand);
        if (lane == 0) s_wslot[buf][wid] = make_uint2(wmax, widx);
        __syncthreads();

        // --- block reduce over 8 warp slots (all warps redundantly) -------
        uint2 ws = s_wslot[buf][lane & (FPS_THR / 32 - 1)];
        unsigned bmax = __reduce_max_sync(0xffffffffu, ws.x);
        cand = (ws.x == bmax) ? ws.y : 0xffffffffu;
        unsigned bidx = __reduce_min_sync(0xffffffffu, cand);

        // --- cluster exchange: broadcast block winner to all 8 peers ------
        if (tid < FPS_CTAS) {
            unsigned long long key =
                ((unsigned long long)bmax << 32) | (unsigned long long)bidx;
            unsigned slot = smem_u32(&s_cslot[buf][rank]);
            asm volatile(
                "{\n\t.reg .b32 ra, rb;\n\t"
                "mapa.shared::cluster.u32 ra, %0, %2;\n\t"
                "st.shared::cluster.b64 [ra], %1;\n\t"
                "mapa.shared::cluster.u32 rb, %3, %2;\n\t"
                "mbarrier.arrive.release.cluster.shared::cluster.b64 _, [rb];\n\t"
                "}"
                :: "r"(slot), "l"(key), "r"(tid), "r"(mbar_addr) : "memory");
        }
        // wait for 8 arrivals; phase parity alternates per iteration
        {
            unsigned parity = (unsigned)((it - 1) & 1);
            asm volatile(
                "{\n\t.reg .pred P1;\n\t"
                "WAIT_%=:\n\t"
                "mbarrier.try_wait.parity.acquire.cluster.shared::cta.b64 P1, [%0], %1;\n\t"
                "@P1 bra DONE_%=;\n\t"
                "bra WAIT_%=;\n\t"
                "DONE_%=:\n\t}"
                :: "r"(mbar_addr), "r"(parity) : "memory");
        }

        // --- cluster reduce over 8 slots (all threads redundantly) --------
        unsigned long long cs = s_cslot[buf][lane & (FPS_CTAS - 1)];
        unsigned cv = (unsigned)(cs >> 32);
        unsigned ci = (unsigned)cs;
        unsigned gmax = __reduce_max_sync(0xffffffffu, cv);
        cand = (cv == gmax) ? ci : 0xffffffffu;
        unsigned gidx = __reduce_min_sync(0xffffffffu, cand);

        qx = posb[gidx * 3 + 0];   // broadcast load, L1-resident
        qy = posb[gidx * 3 + 1];
        qz = posb[gidx * 3 + 2];
        if (rank == 0 && tid == 0) {
            size_t o = POS_S_OFF + ((size_t)b * M_ + it) * 3;
            out[o + 0] = qx; out[o + 1] = qy; out[o + 2] = qz;
            out[BATCH_OFF + (size_t)b * M_ + it] = (float)b;
            asm volatile("st.release.gpu.u32 [%0], %1;"
                         :: "l"(&g_iter[b]), "r"((unsigned)(it + 1)) : "memory");
        }
    }

    asm volatile("barrier.cluster.arrive.aligned;" ::: "memory");
    asm volatile("barrier.cluster.wait.aligned;" ::: "memory");
}

// ===========================================================================
// SA role: 80 persistent worker blocks (blocks 64..143), exactly one per SM
// (grid 144 <= 148 SMs, contiguous-modular placement => no SM sharing with
// fps). Worker w processes m = w, w+80, ... ; warp b handles center (b, m).
// Gate per m: tid0 polls min_b g_iter[b] >= m+1 (nanosleep backoff), then
// __syncthreads; each thread re-reads g_iter[warp] with ld.acquire.gpu to
// own the happens-before edge to fps's pos_s stores.
// Task body identical to the Round-6 sa_kernel (448us standalone).
// ===========================================================================
__device__ __forceinline__ void sa_role(const float* __restrict__ x,
                                        const float* __restrict__ pos,
                                        const float* __restrict__ W1,
                                        const float* __restrict__ b1,
                                        const float* __restrict__ W2,
                                        const float* __restrict__ b2,
                                        float* __restrict__ out) {
    __shared__ __align__(16) float sW1[64][16];    // W1^T
    __shared__ float sb1[64];
    __shared__ __align__(16) float sW2[128][64];   // W2^T
    __shared__ float sb2[128];
    __shared__ int   s_nbr[8][KNB];

    const int tid = threadIdx.x;
    for (int i = tid; i < 64 * 16; i += 256) {
        int j = i >> 4, k = i & 15;
        sW1[j][k] = W1[k * 64 + j];
    }
    for (int i = tid; i < 128 * 64; i += 256) {
        int j = i >> 6, k = i & 63;
        sW2[j][k] = W2[k * 128 + j];
    }
    if (tid < 64)  sb1[tid] = b1[tid];
    if (tid < 128) sb2[tid] = b2[tid];
    __syncthreads();

    const int warp = tid >> 5;
    const int lane = tid & 31;
    const int w    = blockIdx.x - 64;         // worker id 0..79
    const int b    = warp;                    // cloud
    const float* posb = pos + (size_t)b * N_ * 3;
    const float* xb   = x   + (size_t)b * N_ * DIN;

    for (int m = w; m < M_; m += SA_WORKERS) {
        // --- gate: all 8 clouds must have published center m --------------
        if (tid == 0) {
            const unsigned need = (unsigned)(m + 1);
            for (;;) {
                unsigned mn = 0xffffffffu;
#pragma unroll
                for (int bb = 0; bb < B_; bb++) {
                    unsigned v;
                    asm volatile("ld.acquire.gpu.u32 %0, [%1];"
                                 : "=r"(v) : "l"(&g_iter[bb]) : "memory");
                    mn = min(mn, v);
                }
                if (mn >= need) break;
                __nanosleep(256);
            }
        }
        __syncthreads();
        // own the acquire edge in every thread (monotonic flag, guaranteed
        // >= m+1 now; the load itself establishes ordering for pos_s reads)
        {
            unsigned v;
            asm volatile("ld.acquire.gpu.u32 %0, [%1];"
                         : "=r"(v) : "l"(&g_iter[b]) : "memory");
            (void)v;
        }

        const int c = b * M_ + m;             // global center id
        const float cx = out[POS_S_OFF + (size_t)c * 3 + 0];
        const float cy = out[POS_S_OFF + (size_t)c * 3 + 1];
        const float cz = out[POS_S_OFF + (size_t)c * 3 + 2];

        // --- Ball query: first KNB in-ball points by ascending index ------
        int count = 0;
        for (int base = 0; base < N_ && count < KNB; base += 32) {
            const int n = base + lane;
            float d = d2_exact(posb[n * 3 + 0], posb[n * 3 + 1],
                               posb[n * 3 + 2], cx, cy, cz);
            const bool within = (d <= R2);
            const unsigned mask = __ballot_sync(0xffffffffu, within);
            const int pre = __popc(mask & ((1u << lane) - 1u));
            if (within && (count + pre) < KNB) s_nbr[warp][count + pre] = n;
            count += __popc(mask);
            if (count > KNB) count = KNB;
        }
        __syncwarp();
        const bool valid = (lane < count);
        const int  nbr   = valid ? s_nbr[warp][lane] : s_nbr[warp][0];

        // --- Gather features ----------------------------------------------
        float f[16];
#pragma unroll
        for (int k = 0; k < DIN; k++) f[k] = xb[(size_t)nbr * DIN + k];
        f[13] = posb[nbr * 3 + 0] - cx;
        f[14] = posb[nbr * 3 + 1] - cy;
        f[15] = posb[nbr * 3 + 2] - cz;

        // --- Layer 1: 16 -> 64, ReLU (h1 stays in registers) --------------
        float h1[64];
#pragma unroll
        for (int j = 0; j < 64; j++) {
            float acc = sb1[j];
            const float4* wp = reinterpret_cast<const float4*>(&sW1[j][0]);
#pragma unroll
            for (int k4 = 0; k4 < 4; k4++) {
                float4 w4 = wp[k4];
                acc = fmaf(f[4 * k4 + 0], w4.x, acc);
                acc = fmaf(f[4 * k4 + 1], w4.y, acc);
                acc = fmaf(f[4 * k4 + 2], w4.z, acc);
                acc = fmaf(f[4 * k4 + 3], w4.w, acc);
            }
            h1[j] = fmaxf(acc, 0.0f);
        }

        // --- Layer 2: 64 -> 128, ReLU, masked warp-max (redux.sync) -------
        float r0, r1, r2, r3;
#pragma unroll
        for (int jo = 0; jo < 4; jo++) {
#pragma unroll 1
            for (int ji = 0; ji < 32; ji++) {
                const int j = jo * 32 + ji;
                float a0 = sb2[j], a1 = 0.0f;
                const float4* wp = reinterpret_cast<const float4*>(&sW2[j][0]);
#pragma unroll
                for (int k4 = 0; k4 < 8; k4++) {
                    float4 wA = wp[k4];
                    float4 wB = wp[k4 + 8];
                    a0 = fmaf(h1[4 * k4 + 0],      wA.x, a0);
                    a0 = fmaf(h1[4 * k4 + 1],      wA.y, a0);
                    a0 = fmaf(h1[4 * k4 + 2],      wA.z, a0);
                    a0 = fmaf(h1[4 * k4 + 3],      wA.w, a0);
                    a1 = fmaf(h1[32 + 4 * k4 + 0], wB.x, a1);
                    a1 = fmaf(h1[32 + 4 * k4 + 1], wB.y, a1);
                    a1 = fmaf(h1[32 + 4 * k4 + 2], wB.z, a1);
                    a1 = fmaf(h1[32 + 4 * k4 + 3], wB.w, a1);
                }
                float acc = fmaxf(a0 + a1, 0.0f);
                // invalid slots contribute 0: safe because ReLU >= 0 and
                // the center itself is always in-ball (d^2 = 0 <= R^2).
                if (!valid) acc = 0.0f;
                // acc >= 0 -> f32 bits monotonic under unsigned max
                unsigned red = __reduce_max_sync(0xffffffffu,
                                                 __float_as_uint(acc));
                if (lane == ji) {
                    float rv = __uint_as_float(red);
                    if (jo == 0) r0 = rv;
                    else if (jo == 1) r1 = rv;
                    else if (jo == 2) r2 = rv;
                    else r3 = rv;
                }
            }
        }

        float* o = out + X_OUT_OFF + (size_t)c * 128;
        o[lane +  0] = r0;
        o[lane + 32] = r1;
        o[lane + 64] = r2;
        o[lane + 96] = r3;
    }
}

// ===========================================================================
// Fused kernel: blocks 0..63 = FPS (8 clusters x 8 CTAs), blocks 64..143 =
// 80 persistent SA workers. 144 blocks <= 148 SMs => one block per SM, all
// wave-1 resident: sa never shares an SM with fps and can never starve it.
// ===========================================================================
__global__ void __launch_bounds__(256)
__cluster_dims__(FPS_CTAS, 1, 1)
fused_kernel(const float* __restrict__ x, const float* __restrict__ pos,
             const float* __restrict__ W1, const float* __restrict__ b1,
             const float* __restrict__ W2, const float* __restrict__ b2,
             float* __restrict__ out) {
    if (blockIdx.x < 64) {
        fps_role(pos, out);
    } else {
        sa_role(x, pos, W1, b1, W2, b2, out);
    }
}

// ===========================================================================
extern "C" void kernel_launch(void* const* d_in, const int* in_sizes, int n_in,
                              void* d_out, int out_size) {
    (void)in_sizes; (void)n_in; (void)out_size;
    const float* x   = (const float*)d_in[0];   // [B, N, 13]
    const float* pos = (const float*)d_in[1];   // [B, N, 3]
    // d_in[2] = batch (int32) — always broadcast arange(B), recomputed directly
    const float* W1  = (const float*)d_in[3];   // [16, 64]
    const float* b1  = (const float*)d_in[4];   // [64]
    const float* W2  = (const float*)d_in[5];   // [64, 128]
    const float* b2  = (const float*)d_in[6];   // [128]
    float* out = (float*)d_out;

    // Reset fps progress flags on every graph replay (stale flags + poisoned
    // output buffer would otherwise let sa read garbage centers).
    void* p_iter = nullptr;
    cudaGetSymbolAddress(&p_iter, g_iter);
    cudaMemsetAsync(p_iter, 0, sizeof(unsigned) * B_, 0);

    fused_kernel<<<GRID_TOT, 256>>>(x, pos, W1, b1, W2, b2, out);
}

// round 13
// speedup vs baseline: 1.5517x; 1.3670x over previous
#include <cuda_runtime.h>
#include <cuda_bf16.h>

// Problem constants
#define B_    8
#define N_    8192
#define DIN   13
#define M_    2048
#define KNB   32
#define R2    0.04f

// Output layout (single float32 buffer, outputs concatenated in return order):
//   x_out  [B][M][128]  floats
//   pos_s  [B][M][3]    floats
//   batch_s[B][M]       floats (values 0..7, exact)
#define X_OUT_OFF 0
#define POS_S_OFF (B_ * M_ * 128)            // 2097152
#define BATCH_OFF (POS_S_OFF + B_ * M_ * 3)  // 2146304

// Per-cloud FPS progress: g_iter[b] = (last published iteration) + 1.
// Published every 16 iterations (amortized release). Reset to 0 by a
// memset node at the head of the graph on every replay.
__device__ unsigned g_iter[B_];

#define SA_WORKERS 80
#define GRID_TOT   (64 + SA_WORKERS)   // 144 blocks, one per SM

// ---------------------------------------------------------------------------
// Distance with NO fma contraction: must bit-match jnp.sum((a-b)**2, -1)
// ---------------------------------------------------------------------------
__device__ __forceinline__ float d2_exact(float ax, float ay, float az,
                                          float bx, float by, float bz) {
    float dx = ax - bx, dy = ay - by, dz = az - bz;
    return __fadd_rn(__fadd_rn(__fmul_rn(dx, dx), __fmul_rn(dy, dy)),
                     __fmul_rn(dz, dz));
}

__device__ __forceinline__ unsigned smem_u32(const void* p) {
    return (unsigned)__cvta_generic_to_shared(p);
}

// ===========================================================================
// FPS role: cluster of 8 CTAs per batch element (blocks 0..63).
// Round-6 design (best measured 1726us): two-stage reduce then 8-arrival
// DSMEM exchange with mbarrier + try_wait sleep. Progress flag published
// only every 16 iterations so the strong store stays off the critical chain.
// ===========================================================================
#define FPS_CTAS 8
#define FPS_THR  256
#define FPS_TOT  (FPS_CTAS * FPS_THR)   // 2048
#define FPS_PPT  (N_ / FPS_TOT)         // 4

__device__ __forceinline__ void fps_role(const float* __restrict__ pos,
                                         float* __restrict__ out) {
    const int rank = blockIdx.x % FPS_CTAS;
    const int b    = blockIdx.x / FPS_CTAS;
    const int tid  = threadIdx.x;
    const int lane = tid & 31;
    const int wid  = tid >> 5;
    const float* posb = pos + (size_t)b * N_ * 3;

    __shared__ unsigned long long s_mbar;
    __shared__ uint2              s_wslot[2][FPS_THR / 32];
    __shared__ unsigned long long s_cslot[2][FPS_CTAS];

    const unsigned mbar_addr = smem_u32(&s_mbar);
    if (tid == 0) {
        asm volatile("mbarrier.init.shared.b64 [%0], %1;"
                     :: "r"(mbar_addr), "r"(FPS_CTAS) : "memory");
    }
    __syncthreads();
    // All cluster mbarriers initialized before any peer arrives on them.
    asm volatile("barrier.cluster.arrive.aligned;" ::: "memory");
    asm volatile("barrier.cluster.wait.aligned;" ::: "memory");

    float px[FPS_PPT], py[FPS_PPT], pz[FPS_PPT], mind[FPS_PPT];
    const int tg = rank * FPS_THR + tid;    // thread id within the cloud
#pragma unroll
    for (int k = 0; k < FPS_PPT; k++) {
        int g = tg + k * FPS_TOT;
        px[k]   = posb[g * 3 + 0];
        py[k]   = posb[g * 3 + 1];
        pz[k]   = posb[g * 3 + 2];
        mind[k] = 1e10f;
    }

    // First sample is index 0.
    float qx = posb[0], qy = posb[1], qz = posb[2];
    if (rank == 0 && tid == 0) {
        size_t o = POS_S_OFF + ((size_t)b * M_) * 3;
        out[o + 0] = qx; out[o + 1] = qy; out[o + 2] = qz;
        out[BATCH_OFF + (size_t)b * M_] = (float)b;
        asm volatile("st.release.gpu.u32 [%0], %1;"
                     :: "l"(&g_iter[b]), "r"(1u) : "memory");
    }

    for (int it = 1; it < M_; it++) {
        const int buf = it & 1;

        // --- per-thread update + argmax (smallest index on ties) ----------
        float bv = -1.0f; int bi = 0;
#pragma unroll
        for (int k = 0; k < FPS_PPT; k++) {
            float d  = d2_exact(px[k], py[k], pz[k], qx, qy, qz);
            float mv = fminf(mind[k], d);
            mind[k]  = mv;
            if (mv > bv) { bv = mv; bi = tg + k * FPS_TOT; }
        }
        unsigned vb = __float_as_uint(bv);   // bv >= 0 -> monotonic bits

        // --- warp reduce: max value, then min index among ties ------------
        unsigned wmax = __reduce_max_sync(0xffffffffu, vb);
        unsigned cand = (vb == wmax) ? (unsigned)bi : 0xffffffffu;
        unsigned widx = __reduce_min_sync(0xffffffffu, cand);
        if (lane == 0) s_wslot[buf][wid] = make_uint2(wmax, widx);
        __syncthreads();

        // --- block reduce over 8 warp slots (all warps redundantly) -------
        uint2 ws = s_wslot[buf][lane & (FPS_THR / 32 - 1)];
        unsigned bmax = __reduce_max_sync(0xffffffffu, ws.x);
        cand = (ws.x == bmax) ? ws.y : 0xffffffffu;
        unsigned bidx = __reduce_min_sync(0xffffffffu, cand);

        // --- cluster exchange: broadcast block winner to all 8 peers ------
        if (tid < FPS_CTAS) {
            unsigned long long key =
                ((unsigned long long)bmax << 32) | (unsigned long long)bidx;
            unsigned slot = smem_u32(&s_cslot[buf][rank]);
            asm volatile(
                "{\n\t.reg .b32 ra, rb;\n\t"
                "mapa.shared::cluster.u32 ra, %0, %2;\n\t"
                "st.shared::cluster.b64 [ra], %1;\n\t"
                "mapa.shared::cluster.u32 rb, %3, %2;\n\t"
                "mbarrier.arrive.release.cluster.shared::cluster.b64 _, [rb];\n\t"
                "}"
                :: "r"(slot), "l"(key), "r"(tid), "r"(mbar_addr) : "memory");
        }
        // wait for 8 arrivals; phase parity alternates per iteration
        {
            unsigned parity = (unsigned)((it - 1) & 1);
            asm volatile(
                "{\n\t.reg .pred P1;\n\t"
                "WAIT_%=:\n\t"
                "mbarrier.try_wait.parity.acquire.cluster.shared::cta.b64 P1, [%0], %1;\n\t"
                "@P1 bra DONE_%=;\n\t"
                "bra WAIT_%=;\n\t"
                "DONE_%=:\n\t}"
                :: "r"(mbar_addr), "r"(parity) : "memory");
        }

        // --- cluster reduce over 8 slots (all threads redundantly) --------
        unsigned long long cs = s_cslot[buf][lane & (FPS_CTAS - 1)];
        unsigned cv = (unsigned)(cs >> 32);
        unsigned ci = (unsigned)cs;
        unsigned gmax = __reduce_max_sync(0xffffffffu, cv);
        cand = (cv == gmax) ? ci : 0xffffffffu;
        unsigned gidx = __reduce_min_sync(0xffffffffu, cand);

        qx = posb[gidx * 3 + 0];   // broadcast load, L1-resident
        qy = posb[gidx * 3 + 1];
        qz = posb[gidx * 3 + 2];
        if (rank == 0 && tid == 0) {
            size_t o = POS_S_OFF + ((size_t)b * M_ + it) * 3;
            out[o + 0] = qx; out[o + 1] = qy; out[o + 2] = qz;
            out[BATCH_OFF + (size_t)b * M_ + it] = (float)b;
            // Publish progress only every 16 iterations: the strong store
            // (and its contention with pollers) stays off the serial chain.
            // it=15 -> flag 16, ..., it=2047 -> flag 2048 (covers all m).
            if ((it & 15) == 15) {
                asm volatile("st.release.gpu.u32 [%0], %1;"
                             :: "l"(&g_iter[b]), "r"((unsigned)(it + 1))
                             : "memory");
            }
        }
    }

    asm volatile("barrier.cluster.arrive.aligned;" ::: "memory");
    asm volatile("barrier.cluster.wait.aligned;" ::: "memory");
}

// ===========================================================================
// SA role: 80 persistent worker blocks (blocks 64..143), one per SM.
// Worker w processes m = w, w+80, ... ; warp b handles center (b, m).
// Gate per m: tid0 polls min_b g_iter[b] >= m+1 with ADAPTIVE backoff
// (16us sleep while far from ready, 1us when close) so idle pollers do not
// congest the flag line. Task body = Round-6 sa_kernel (448us standalone).
// ===========================================================================
__device__ __forceinline__ void sa_role(const float* __restrict__ x,
                                        const float* __restrict__ pos,
                                        const float* __restrict__ W1,
                                        const float* __restrict__ b1,
                                        const float* __restrict__ W2,
                                        const float* __restrict__ b2,
                                        float* __restrict__ out) {
    __shared__ __align__(16) float sW1[64][16];    // W1^T
    __shared__ float sb1[64];
    __shared__ __align__(16) float sW2[128][64];   // W2^T
    __shared__ float sb2[128];
    __shared__ int   s_nbr[8][KNB];

    const int tid = threadIdx.x;
    for (int i = tid; i < 64 * 16; i += 256) {
        int j = i >> 4, k = i & 15;
        sW1[j][k] = W1[k * 64 + j];
    }
    for (int i = tid; i < 128 * 64; i += 256) {
        int j = i >> 6, k = i & 63;
        sW2[j][k] = W2[k * 128 + j];
    }
    if (tid < 64)  sb1[tid] = b1[tid];
    if (tid < 128) sb2[tid] = b2[tid];
    __syncthreads();

    const int warp = tid >> 5;
    const int lane = tid & 31;
    const int w    = blockIdx.x - 64;         // worker id 0..79
    const int b    = warp;                    // cloud
    const float* posb = pos + (size_t)b * N_ * 3;
    const float* xb   = x   + (size_t)b * N_ * DIN;

    for (int m = w; m < M_; m += SA_WORKERS) {
        // --- gate: all 8 clouds must have published center m --------------
        if (tid == 0) {
            const unsigned need = (unsigned)(m + 1);
            for (;;) {
                unsigned mn = 0xffffffffu;
#pragma unroll
                for (int bb = 0; bb < B_; bb++) {
                    unsigned v;
                    asm volatile("ld.acquire.gpu.u32 %0, [%1];"
                                 : "=r"(v) : "l"(&g_iter[bb]) : "memory");
                    mn = min(mn, v);
                }
                if (mn >= need) break;
                // adaptive backoff: sleep long while far from ready
                __nanosleep((need - mn) > 32 ? 16384u : 1024u);
            }
        }
        __syncthreads();
        // own the acquire edge in every thread (flag is monotonic and now
        // >= m+1; the acquire load orders subsequent pos_s reads)
        {
            unsigned v;
            asm volatile("ld.acquire.gpu.u32 %0, [%1];"
                         : "=r"(v) : "l"(&g_iter[b]) : "memory");
            (void)v;
        }

        const int c = b * M_ + m;             // global center id
        const float cx = out[POS_S_OFF + (size_t)c * 3 + 0];
        const float cy = out[POS_S_OFF + (size_t)c * 3 + 1];
        const float cz = out[POS_S_OFF + (size_t)c * 3 + 2];

        // --- Ball query: first KNB in-ball points by ascending index ------
        int count = 0;
        for (int base = 0; base < N_ && count < KNB; base += 32) {
            const int n = base + lane;
            float d = d2_exact(posb[n * 3 + 0], posb[n * 3 + 1],
                               posb[n * 3 + 2], cx, cy, cz);
            const bool within = (d <= R2);
            const unsigned mask = __ballot_sync(0xffffffffu, within);
            const int pre = __popc(mask & ((1u << lane) - 1u));
            if (within && (count + pre) < KNB) s_nbr[warp][count + pre] = n;
            count += __popc(mask);
            if (count > KNB) count = KNB;
        }
        __syncwarp();
        const bool valid = (lane < count);
        const int  nbr   = valid ? s_nbr[warp][lane] : s_nbr[warp][0];

        // --- Gather features ----------------------------------------------
        float f[16];
#pragma unroll
        for (int k = 0; k < DIN; k++) f[k] = xb[(size_t)nbr * DIN + k];
        f[13] = posb[nbr * 3 + 0] - cx;
        f[14] = posb[nbr * 3 + 1] - cy;
        f[15] = posb[nbr * 3 + 2] - cz;

        // --- Layer 1: 16 -> 64, ReLU (h1 stays in registers) --------------
        float h1[64];
#pragma unroll
        for (int j = 0; j < 64; j++) {
            float acc = sb1[j];
            const float4* wp = reinterpret_cast<const float4*>(&sW1[j][0]);
#pragma unroll
            for (int k4 = 0; k4 < 4; k4++) {
                float4 w4 = wp[k4];
                acc = fmaf(f[4 * k4 + 0], w4.x, acc);
                acc = fmaf(f[4 * k4 + 1], w4.y, acc);
                acc = fmaf(f[4 * k4 + 2], w4.z, acc);
                acc = fmaf(f[4 * k4 + 3], w4.w, acc);
            }
            h1[j] = fmaxf(acc, 0.0f);
        }

        // --- Layer 2: 64 -> 128, ReLU, masked warp-max (redux.sync) -------
        float r0, r1, r2, r3;
#pragma unroll
        for (int jo = 0; jo < 4; jo++) {
#pragma unroll 1
            for (int ji = 0; ji < 32; ji++) {
                const int j = jo * 32 + ji;
                float a0 = sb2[j], a1 = 0.0f;
                const float4* wp = reinterpret_cast<const float4*>(&sW2[j][0]);
#pragma unroll
                for (int k4 = 0; k4 < 8; k4++) {
                    float4 wA = wp[k4];
                    float4 wB = wp[k4 + 8];
                    a0 = fmaf(h1[4 * k4 + 0],      wA.x, a0);
                    a0 = fmaf(h1[4 * k4 + 1],      wA.y, a0);
                    a0 = fmaf(h1[4 * k4 + 2],      wA.z, a0);
                    a0 = fmaf(h1[4 * k4 + 3],      wA.w, a0);
                    a1 = fmaf(h1[32 + 4 * k4 + 0], wB.x, a1);
                    a1 = fmaf(h1[32 + 4 * k4 + 1], wB.y, a1);
                    a1 = fmaf(h1[32 + 4 * k4 + 2], wB.z, a1);
                    a1 = fmaf(h1[32 + 4 * k4 + 3], wB.w, a1);
                }
                float acc = fmaxf(a0 + a1, 0.0f);
                // invalid slots contribute 0: safe because ReLU >= 0 and
                // the center itself is always in-ball (d^2 = 0 <= R^2).
                if (!valid) acc = 0.0f;
                // acc >= 0 -> f32 bits monotonic under unsigned max
                unsigned red = __reduce_max_sync(0xffffffffu,
                                                 __float_as_uint(acc));
                if (lane == ji) {
                    float rv = __uint_as_float(red);
                    if (jo == 0) r0 = rv;
                    else if (jo == 1) r1 = rv;
                    else if (jo == 2) r2 = rv;
                    else r3 = rv;
                }
            }
        }

        float* o = out + X_OUT_OFF + (size_t)c * 128;
        o[lane +  0] = r0;
        o[lane + 32] = r1;
        o[lane + 64] = r2;
        o[lane + 96] = r3;
    }
}

// ===========================================================================
// Fused kernel: blocks 0..63 = FPS (8 clusters x 8 CTAs), blocks 64..143 =
// 80 persistent SA workers. 144 blocks <= 148 SMs => one block per SM, all
// wave-1 resident: sa never shares an SM with fps and can never starve it.
// ===========================================================================
__global__ void __launch_bounds__(256)
__cluster_dims__(FPS_CTAS, 1, 1)
fused_kernel(const float* __restrict__ x, const float* __restrict__ pos,
             const float* __restrict__ W1, const float* __restrict__ b1,
             const float* __restrict__ W2, const float* __restrict__ b2,
             float* __restrict__ out) {
    if (blockIdx.x < 64) {
        fps_role(pos, out);
    } else {
        sa_role(x, pos, W1, b1, W2, b2, out);
    }
}

// ===========================================================================
extern "C" void kernel_launch(void* const* d_in, const int* in_sizes, int n_in,
                              void* d_out, int out_size) {
    (void)in_sizes; (void)n_in; (void)out_size;
    const float* x   = (const float*)d_in[0];   // [B, N, 13]
    const float* pos = (const float*)d_in[1];   // [B, N, 3]
    // d_in[2] = batch (int32) — always broadcast arange(B), recomputed directly
    const float* W1  = (const float*)d_in[3];   // [16, 64]
    const float* b1  = (const float*)d_in[4];   // [64]
    const float* W2  = (const float*)d_in[5];   // [64, 128]
    const float* b2  = (const float*)d_in[6];   // [128]
    float* out = (float*)d_out;

    // Reset fps progress flags on every graph replay (stale flags + poisoned
    // output buffer would otherwise let sa read garbage centers).
    void* p_iter = nullptr;
    cudaGetSymbolAddress(&p_iter, g_iter);
    cudaMemsetAsync(p_iter, 0, sizeof(unsigned) * B_, 0);

    fused_kernel<<<GRID_TOT, 256>>>(x, pos, W1, b1, W2, b2, out);
}

// round 15
// speedup vs baseline: 2.5268x; 1.6284x over previous
#include <cuda_runtime.h>
#include <cuda_bf16.h>

// Problem constants
#define B_    8
#define N_    8192
#define DIN   13
#define M_    2048
#define KNB   32
#define R2    0.04f

// Output layout (single float32 buffer, outputs concatenated in return order):
//   x_out  [B][M][128]  floats
//   pos_s  [B][M][3]    floats
//   batch_s[B][M]       floats (values 0..7, exact)
#define X_OUT_OFF 0
#define POS_S_OFF (B_ * M_ * 128)            // 2097152
#define BATCH_OFF (POS_S_OFF + B_ * M_ * 3)  // 2146304

// Per-cloud FPS progress: g_iter[b] = (last published iteration) + 1.
// Published every 16 iterations (amortized release). Reset to 0 by a
// memset node at the head of the graph on every replay.
__device__ unsigned g_iter[B_];

#define SA_WORKERS 80
#define GRID_TOT   (64 + SA_WORKERS)   // 144 blocks, one per SM

// ---------------------------------------------------------------------------
// Distance with NO fma contraction: must bit-match jnp.sum((a-b)**2, -1)
// ---------------------------------------------------------------------------
__device__ __forceinline__ float d2_exact(float ax, float ay, float az,
                                          float bx, float by, float bz) {
    float dx = ax - bx, dy = ay - by, dz = az - bz;
    return __fadd_rn(__fadd_rn(__fmul_rn(dx, dx), __fmul_rn(dy, dy)),
                     __fmul_rn(dz, dz));
}

__device__ __forceinline__ unsigned smem_u32(const void* p) {
    return (unsigned)__cvta_generic_to_shared(p);
}

// ===========================================================================
// FPS role: cluster of 8 CTAs per batch element (blocks 0..63).
// Mbarrier-free exchange: the 8-byte winner word IS the signal.
// Per iteration:
//   1. all warps: update running mins, per-thread argmax (tie -> min index),
//      warp redux, lane0 writes warp winner to s_wslot[buf][wid].
//   2. __syncthreads.
//   3. warp 0 only: block redux over the 8 warp slots; lanes 0..7 pack
//        key = [val:32 | (8191-idx):13 | it:19]
//      and issue ONE st.shared::cluster.b64 into slot[rank] of CTA 'lane'.
//      (no mbarrier: no second remote hop, no arrival serialization)
//   4. all warps: poll the 8 LOCAL slots (lane&7) with ld.volatile until
//      every embedded tag == it, then u64-max redux (== val desc, idx asc).
// Safety: b64 aligned stores are single-copy atomic; the tag makes stale
// reads loop; double-buffered slots + (my send for it+2 happens-after my
// consumption of it+1, which happens-after every peer consumed it) prevent
// WAR/ABA. Only 8 warps poll local smem -> no port-contention feedback.
// ===========================================================================
#define FPS_CTAS 8
#define FPS_THR  256
#define FPS_TOT  (FPS_CTAS * FPS_THR)   // 2048
#define FPS_PPT  (N_ / FPS_TOT)         // 4

__device__ __forceinline__ void fps_role(const float* __restrict__ pos,
                                         float* __restrict__ out) {
    const int rank = blockIdx.x % FPS_CTAS;
    const int b    = blockIdx.x / FPS_CTAS;
    const int tid  = threadIdx.x;
    const int lane = tid & 31;
    const int wid  = tid >> 5;
    const float* posb = pos + (size_t)b * N_ * 3;

    __shared__ uint2 s_wslot[2][FPS_THR / 32];
    __shared__ __align__(16) unsigned long long s_cslot[2][FPS_CTAS];

    if (tid < FPS_CTAS) { s_cslot[0][tid] = 0ull; s_cslot[1][tid] = 0ull; }
    __syncthreads();
    // Slots zeroed in every CTA before any peer may store into them.
    asm volatile("barrier.cluster.arrive.aligned;" ::: "memory");
    asm volatile("barrier.cluster.wait.aligned;" ::: "memory");

    float px[FPS_PPT], py[FPS_PPT], pz[FPS_PPT], mind[FPS_PPT];
    const int tg = rank * FPS_THR + tid;    // thread id within the cloud
#pragma unroll
    for (int k = 0; k < FPS_PPT; k++) {
        int g = tg + k * FPS_TOT;
        px[k]   = posb[g * 3 + 0];
        py[k]   = posb[g * 3 + 1];
        pz[k]   = posb[g * 3 + 2];
        mind[k] = 1e10f;
    }

    // First sample is index 0.
    float qx = posb[0], qy = posb[1], qz = posb[2];
    if (rank == 0 && tid == 0) {
        size_t o = POS_S_OFF + ((size_t)b * M_) * 3;
        out[o + 0] = qx; out[o + 1] = qy; out[o + 2] = qz;
        out[BATCH_OFF + (size_t)b * M_] = (float)b;
        asm volatile("st.release.gpu.u32 [%0], %1;"
                     :: "l"(&g_iter[b]), "r"(1u) : "memory");
    }

    // Poll address for this lane (slot lane&7), both buffers.
    const unsigned pslot[2] = { smem_u32(&s_cslot[0][lane & 7]),
                                smem_u32(&s_cslot[1][lane & 7]) };
    // Send target offset (this CTA's slot index within each peer CTA).
    const unsigned sslot[2] = { smem_u32(&s_cslot[0][rank]),
                                smem_u32(&s_cslot[1][rank]) };

    for (int it = 1; it < M_; it++) {
        const int buf = it & 1;

        // --- 1. per-thread update + argmax (smallest index on ties) -------
        float bv = -1.0f; int bi = 0;
#pragma unroll
        for (int k = 0; k < FPS_PPT; k++) {
            float d  = d2_exact(px[k], py[k], pz[k], qx, qy, qz);
            float mv = fminf(mind[k], d);
            mind[k]  = mv;
            if (mv > bv) { bv = mv; bi = tg + k * FPS_TOT; }
        }
        unsigned vb = __float_as_uint(bv);   // bv >= 0 -> monotonic bits

        unsigned wmax = __reduce_max_sync(0xffffffffu, vb);
        unsigned cand = (vb == wmax) ? (unsigned)bi : 0xffffffffu;
        unsigned widx = __reduce_min_sync(0xffffffffu, cand);
        if (lane == 0) s_wslot[buf][wid] = make_uint2(wmax, widx);
        __syncthreads();

        // --- 3. warp 0: block redux + single remote store per peer --------
        if (wid == 0) {
            uint2 ws = s_wslot[buf][lane & (FPS_THR / 32 - 1)];
            unsigned bmax = __reduce_max_sync(0xffffffffu, ws.x);
            cand = (ws.x == bmax) ? ws.y : 0xffffffffu;
            unsigned bidx = __reduce_min_sync(0xffffffffu, cand);
            if (lane < FPS_CTAS) {
                const unsigned long long key =
                    ((unsigned long long)bmax << 32) |
                    ((unsigned long long)(8191u - bidx) << 19) |
                    (unsigned)it;
                asm volatile(
                    "{\n\t.reg .b32 ra;\n\t"
                    "mapa.shared::cluster.u32 ra, %0, %2;\n\t"
                    "st.shared::cluster.b64 [ra], %1;\n\t"
                    "}"
                    :: "r"(sslot[buf]), "l"(key), "r"(lane) : "memory");
            }
        }

        // --- 4. all warps: poll local slots until tag == it, then redux ---
        const unsigned tag = (unsigned)it;
        unsigned long long v;
        bool ok = false;
        do {
            asm volatile("ld.volatile.shared.b64 %0, [%1];"
                         : "=l"(v) : "r"(pslot[buf]) : "memory");
            ok = (((unsigned)v & 0x7FFFFu) == tag);
        } while (!__all_sync(0xffffffffu, ok));

        unsigned hi = (unsigned)(v >> 32);
        unsigned lo = (unsigned)v;
        unsigned vmax = __reduce_max_sync(0xffffffffu, hi);
        unsigned lc   = (hi == vmax) ? lo : 0u;
        unsigned lmax = __reduce_max_sync(0xffffffffu, lc);
        const int gidx = 8191 - (int)(lmax >> 19);

        qx = posb[gidx * 3 + 0];   // broadcast load, L1-resident
        qy = posb[gidx * 3 + 1];
        qz = posb[gidx * 3 + 2];
        if (rank == 0 && tid == 0) {
            size_t o = POS_S_OFF + ((size_t)b * M_ + it) * 3;
            out[o + 0] = qx; out[o + 1] = qy; out[o + 2] = qz;
            out[BATCH_OFF + (size_t)b * M_ + it] = (float)b;
            // Publish progress every 16 iterations (strong store stays off
            // the serial chain). it=15 -> 16, ..., it=2047 -> 2048.
            if ((it & 15) == 15) {
                asm volatile("st.release.gpu.u32 [%0], %1;"
                             :: "l"(&g_iter[b]), "r"((unsigned)(it + 1))
                             : "memory");
            }
        }
    }

    asm volatile("barrier.cluster.arrive.aligned;" ::: "memory");
    asm volatile("barrier.cluster.wait.aligned;" ::: "memory");
}

// ===========================================================================
// SA role: 80 persistent worker blocks (blocks 64..143), one per SM.
// Worker w processes m = w, w+80, ... ; warp b handles center (b, m).
// Gate per m: tid0 polls min_b g_iter[b] >= m+1 with adaptive backoff.
// Task body = Round-6 sa_kernel (448us standalone).
// ===========================================================================
__device__ __forceinline__ void sa_role(const float* __restrict__ x,
                                        const float* __restrict__ pos,
                                        const float* __restrict__ W1,
                                        const float* __restrict__ b1,
                                        const float* __restrict__ W2,
                                        const float* __restrict__ b2,
                                        float* __restrict__ out) {
    __shared__ __align__(16) float sW1[64][16];    // W1^T
    __shared__ float sb1[64];
    __shared__ __align__(16) float sW2[128][64];   // W2^T
    __shared__ float sb2[128];
    __shared__ int   s_nbr[8][KNB];

    const int tid = threadIdx.x;
    for (int i = tid; i < 64 * 16; i += 256) {
        int j = i >> 4, k = i & 15;
        sW1[j][k] = W1[k * 64 + j];
    }
    for (int i = tid; i < 128 * 64; i += 256) {
        int j = i >> 6, k = i & 63;
        sW2[j][k] = W2[k * 128 + j];
    }
    if (tid < 64)  sb1[tid] = b1[tid];
    if (tid < 128) sb2[tid] = b2[tid];
    __syncthreads();

    const int warp = tid >> 5;
    const int lane = tid & 31;
    const int w    = blockIdx.x - 64;         // worker id 0..79
    const int b    = warp;                    // cloud
    const float* posb = pos + (size_t)b * N_ * 3;
    const float* xb   = x   + (size_t)b * N_ * DIN;

    for (int m = w; m < M_; m += SA_WORKERS) {
        // --- gate: all 8 clouds must have published center m --------------
        if (tid == 0) {
            const unsigned need = (unsigned)(m + 1);
            for (;;) {
                unsigned mn = 0xffffffffu;
#pragma unroll
                for (int bb = 0; bb < B_; bb++) {
                    unsigned v;
                    asm volatile("ld.acquire.gpu.u32 %0, [%1];"
                                 : "=r"(v) : "l"(&g_iter[bb]) : "memory");
                    mn = min(mn, v);
                }
                if (mn >= need) break;
                // adaptive backoff: sleep long while far from ready
                __nanosleep((need - mn) > 32 ? 16384u : 1024u);
            }
        }
        __syncthreads();
        // own the acquire edge in every thread (flag is monotonic and now
        // >= m+1; the acquire load orders subsequent pos_s reads)
        {
            unsigned v;
            asm volatile("ld.acquire.gpu.u32 %0, [%1];"
                         : "=r"(v) : "l"(&g_iter[b]) : "memory");
            (void)v;
        }

        const int c = b * M_ + m;             // global center id
        const float cx = out[POS_S_OFF + (size_t)c * 3 + 0];
        const float cy = out[POS_S_OFF + (size_t)c * 3 + 1];
        const float cz = out[POS_S_OFF + (size_t)c * 3 + 2];

        // --- Ball query: first KNB in-ball points by ascending index ------
        int count = 0;
        for (int base = 0; base < N_ && count < KNB; base += 32) {
            const int n = base + lane;
            float d = d2_exact(posb[n * 3 + 0], posb[n * 3 + 1],
                               posb[n * 3 + 2], cx, cy, cz);
            const bool within = (d <= R2);
            const unsigned mask = __ballot_sync(0xffffffffu, within);
            const int pre = __popc(mask & ((1u << lane) - 1u));
            if (within && (count + pre) < KNB) s_nbr[warp][count + pre] = n;
            count += __popc(mask);
            if (count > KNB) count = KNB;
        }
        __syncwarp();
        const bool valid = (lane < count);
        const int  nbr   = valid ? s_nbr[warp][lane] : s_nbr[warp][0];

        // --- Gather features ----------------------------------------------
        float f[16];
#pragma unroll
        for (int k = 0; k < DIN; k++) f[k] = xb[(size_t)nbr * DIN + k];
        f[13] = posb[nbr * 3 + 0] - cx;
        f[14] = posb[nbr * 3 + 1] - cy;
        f[15] = posb[nbr * 3 + 2] - cz;

        // --- Layer 1: 16 -> 64, ReLU (h1 stays in registers) --------------
        float h1[64];
#pragma unroll
        for (int j = 0; j < 64; j++) {
            float acc = sb1[j];
            const float4* wp = reinterpret_cast<const float4*>(&sW1[j][0]);
#pragma unroll
            for (int k4 = 0; k4 < 4; k4++) {
                float4 w4 = wp[k4];
                acc = fmaf(f[4 * k4 + 0], w4.x, acc);
                acc = fmaf(f[4 * k4 + 1], w4.y, acc);
                acc = fmaf(f[4 * k4 + 2], w4.z, acc);
                acc = fmaf(f[4 * k4 + 3], w4.w, acc);
            }
            h1[j] = fmaxf(acc, 0.0f);
        }

        // --- Layer 2: 64 -> 128, ReLU, masked warp-max (redux.sync) -------
        float r0, r1, r2, r3;
#pragma unroll
        for (int jo = 0; jo < 4; jo++) {
#pragma unroll 1
            for (int ji = 0; ji < 32; ji++) {
                const int j = jo * 32 + ji;
                float a0 = sb2[j], a1 = 0.0f;
                const float4* wp = reinterpret_cast<const float4*>(&sW2[j][0]);
#pragma unroll
                for (int k4 = 0; k4 < 8; k4++) {
                    float4 wA = wp[k4];
                    float4 wB = wp[k4 + 8];
                    a0 = fmaf(h1[4 * k4 + 0],      wA.x, a0);
                    a0 = fmaf(h1[4 * k4 + 1],      wA.y, a0);
                    a0 = fmaf(h1[4 * k4 + 2],      wA.z, a0);
                    a0 = fmaf(h1[4 * k4 + 3],      wA.w, a0);
                    a1 = fmaf(h1[32 + 4 * k4 + 0], wB.x, a1);
                    a1 = fmaf(h1[32 + 4 * k4 + 1], wB.y, a1);
                    a1 = fmaf(h1[32 + 4 * k4 + 2], wB.z, a1);
                    a1 = fmaf(h1[32 + 4 * k4 + 3], wB.w, a1);
                }
                float acc = fmaxf(a0 + a1, 0.0f);
                // invalid slots contribute 0: safe because ReLU >= 0 and
                // the center itself is always in-ball (d^2 = 0 <= R^2).
                if (!valid) acc = 0.0f;
                // acc >= 0 -> f32 bits monotonic under unsigned max
                unsigned red = __reduce_max_sync(0xffffffffu,
                                                 __float_as_uint(acc));
                if (lane == ji) {
                    float rv = __uint_as_float(red);
                    if (jo == 0) r0 = rv;
                    else if (jo == 1) r1 = rv;
                    else if (jo == 2) r2 = rv;
                    else r3 = rv;
                }
            }
        }

        float* o = out + X_OUT_OFF + (size_t)c * 128;
        o[lane +  0] = r0;
        o[lane + 32] = r1;
        o[lane + 64] = r2;
        o[lane + 96] = r3;
    }
}

// ===========================================================================
// Fused kernel: blocks 0..63 = FPS (8 clusters x 8 CTAs), blocks 64..143 =
// 80 persistent SA workers. 144 blocks <= 148 SMs => one block per SM, all
// wave-1 resident: sa never shares an SM with fps and can never starve it.
// ===========================================================================
__global__ void __launch_bounds__(256)
__cluster_dims__(FPS_CTAS, 1, 1)
fused_kernel(const float* __restrict__ x, const float* __restrict__ pos,
             const float* __restrict__ W1, const float* __restrict__ b1,
             const float* __restrict__ W2, const float* __restrict__ b2,
             float* __restrict__ out) {
    if (blockIdx.x < 64) {
        fps_role(pos, out);
    } else {
        sa_role(x, pos, W1, b1, W2, b2, out);
    }
}

// ===========================================================================
extern "C" void kernel_launch(void* const* d_in, const int* in_sizes, int n_in,
                              void* d_out, int out_size) {
    (void)in_sizes; (void)n_in; (void)out_size;
    const float* x   = (const float*)d_in[0];   // [B, N, 13]
    const float* pos = (const float*)d_in[1];   // [B, N, 3]
    // d_in[2] = batch (int32) — always broadcast arange(B), recomputed directly
    const float* W1  = (const float*)d_in[3];   // [16, 64]
    const float* b1  = (const float*)d_in[4];   // [64]
    const float* W2  = (const float*)d_in[5];   // [64, 128]
    const float* b2  = (const float*)d_in[6];   // [128]
    float* out = (float*)d_out;

    // Reset fps progress flags on every graph replay (stale flags + poisoned
    // output buffer would otherwise let sa read garbage centers).
    void* p_iter = nullptr;
    cudaGetSymbolAddress(&p_iter, g_iter);
    cudaMemsetAsync(p_iter, 0, sizeof(unsigned) * B_, 0);

    fused_kernel<<<GRID_TOT, 256>>>(x, pos, W1, b1, W2, b2, out);
}